// round 15
// baseline (speedup 1.0000x reference)
#include <cuda_runtime.h>
#include <math.h>

#define NB 2
#define SS 2048
#define NH 16
#define HD 64
#define DD 1024
#define D3 3072
#define MTOT (NB*SS)

// Scratch (allocation-free rule: device globals)
__device__ float g_q[NB*NH*SS*HD];     // [B,H,S,hd] (pre-rounded tf32)
__device__ float g_k[NB*NH*SS*HD];
__device__ float g_v[NB*NH*SS*HD];
__device__ float g_attn[MTOT*DD];      // merged heads [B*S, D] (pre-rounded tf32)
__device__ float g_a[MTOT*DD];         // rounded hidden_states
__device__ float g_w[DD*D3];           // rounded w_attn
__device__ float g_wp[DD*DD];          // rounded w_proj

__device__ __forceinline__ unsigned f2t(float x) {
    unsigned u;
    asm("cvt.rna.tf32.f32 %0, %1;" : "=r"(u) : "f"(x));
    return u;
}

__device__ __forceinline__ void mma8(float* d, const unsigned* a, const unsigned* b) {
    asm volatile(
        "mma.sync.aligned.m16n8k8.row.col.f32.tf32.tf32.f32 "
        "{%0,%1,%2,%3}, {%4,%5,%6,%7}, {%8,%9}, {%0,%1,%2,%3};\n"
        : "+f"(d[0]), "+f"(d[1]), "+f"(d[2]), "+f"(d[3])
        : "r"(a[0]), "r"(a[1]), "r"(a[2]), "r"(a[3]), "r"(b[0]), "r"(b[1]));
}

__device__ __forceinline__ void cpa16(unsigned dst, const float* src) {
    asm volatile("cp.async.cg.shared.global [%0], [%1], 16;\n" :: "r"(dst), "l"(src));
}

// ---------------------------------------------------------------------------
// Pre-round: dst[i] = RNA_tf32(src[i]), float4 vectorized.
// ---------------------------------------------------------------------------
__global__ __launch_bounds__(256)
void round_tf32(const float4* __restrict__ src, float4* __restrict__ dst, int n4)
{
    int i = blockIdx.x * blockDim.x + threadIdx.x;
    if (i < n4) {
        float4 v = src[i];
        dst[i] = make_float4(__uint_as_float(f2t(v.x)), __uint_as_float(f2t(v.y)),
                             __uint_as_float(f2t(v.z)), __uint_as_float(f2t(v.w)));
    }
}

// ---------------------------------------------------------------------------
// TF32 GEMM: C[M,N] = A[M,1024] @ W[1024,N] (+bias) (+lora, scatter q/k/v)
// 128x128 CTA tile, BK=32, 128 threads (4 warps 2x2), warp tile 64x64.
// cp.async double-buffered, R12 schedule (best known):
//   issue(it+1) -> wait_group 1 -> sync -> compute -> sync.
// __launch_bounds__(128,3): cap regs at 170 so THREE CTAs/SM co-reside
// (smem 3x71.7KB = 215KB fits) and interleave across barrier phases.
// ---------------------------------------------------------------------------
#define ASTR 36
#define BSTR 136
#define ABUF (128*ASTR)          // 4608 u32
#define BBUF (32*BSTR)           // 4352 u32
#define GBUF (ABUF + BBUF)       // per stage
#define GSMEM (2*GBUF*4)         // bytes = 71680

template<int N, bool QKV>
__global__ __launch_bounds__(128, 3)
void gemm_tf32(const float* __restrict__ A, const float* __restrict__ W,
               const float* __restrict__ bias, const float* __restrict__ lora,
               float* __restrict__ C)
{
    extern __shared__ unsigned sg[];
    const int K = DD;

    const int tid  = threadIdx.x;
    const int warp = tid >> 5, lane = tid & 31;
    const int g = lane >> 2, t = lane & 3;
    const int wm = warp & 1, wn = warp >> 1;         // 2 x 2 warps
    const int bm = blockIdx.y * 128, bn = blockIdx.x * 128;

    const unsigned sbA = (unsigned)__cvta_generic_to_shared(sg);
    const unsigned sbB = sbA + ABUF * 4;

    // issue cp.async for k-tile `it` into stage `buf`
    auto issue = [&](int it, int buf) {
        const unsigned stg = (unsigned)buf * (GBUF * 4);
        const int k0 = it * 32;
#pragma unroll
        for (int i = 0; i < 8; i++) {
            int c = tid + 128 * i;
            int row = c >> 3, kq = c & 7;
            cpa16(sbA + stg + (row * ASTR + kq * 4) * 4,
                  A + (size_t)(bm + row) * K + k0 + kq * 4);
        }
#pragma unroll
        for (int i = 0; i < 8; i++) {
            int c = tid + 128 * i;
            int k = c >> 5, nq = c & 31;
            cpa16(sbB + stg + (k * BSTR + nq * 4) * 4,
                  W + (size_t)(k0 + k) * N + bn + nq * 4);
        }
        asm volatile("cp.async.commit_group;\n" ::: "memory");
    };

    float acc[4][8][4];
#pragma unroll
    for (int mf = 0; mf < 4; mf++)
#pragma unroll
        for (int nf = 0; nf < 8; nf++)
#pragma unroll
            for (int e = 0; e < 4; e++) acc[mf][nf][e] = 0.f;

    issue(0, 0);

    const int NT = K / 32;
    for (int it = 0; it < NT; ++it) {
        if (it < NT - 1) {
            issue(it + 1, (it + 1) & 1);
            asm volatile("cp.async.wait_group 1;\n" ::: "memory");
        } else {
            asm volatile("cp.async.wait_group 0;\n" ::: "memory");
        }
        __syncthreads();

        const unsigned* Ac = sg + (it & 1) * GBUF;
        const unsigned* Bc = Ac + ABUF;
#pragma unroll
        for (int ks = 0; ks < 4; ks++) {
            const int kb = ks * 8;
            unsigned ua[4][4];
#pragma unroll
            for (int mf = 0; mf < 4; mf++) {
                int rbm = wm * 64 + mf * 16;
                ua[mf][0] = Ac[(rbm + g) * ASTR + kb + t];
                ua[mf][1] = Ac[(rbm + g + 8) * ASTR + kb + t];
                ua[mf][2] = Ac[(rbm + g) * ASTR + kb + t + 4];
                ua[mf][3] = Ac[(rbm + g + 8) * ASTR + kb + t + 4];
            }
#pragma unroll
            for (int nf = 0; nf < 8; nf++) {
                unsigned ub[2];
                int col = wn * 64 + nf * 8 + g;
                ub[0] = Bc[(kb + t) * BSTR + col];
                ub[1] = Bc[(kb + t + 4) * BSTR + col];
                mma8(acc[0][nf], ua[0], ub);
                mma8(acc[1][nf], ua[1], ub);
                mma8(acc[2][nf], ua[2], ub);
                mma8(acc[3][nf], ua[3], ub);
            }
        }

        if (it < NT - 1) __syncthreads();   // all done reading this buf
    }

    // epilogue
#pragma unroll
    for (int mf = 0; mf < 4; mf++) {
#pragma unroll
        for (int nf = 0; nf < 8; nf++) {
            int c = bn + wn * 64 + nf * 8 + 2 * t;
            float2 bi = *(const float2*)(bias + c);
#pragma unroll
            for (int half = 0; half < 2; half++) {
                int r = bm + wm * 64 + mf * 16 + g + half * 8;
                float v0 = acc[mf][nf][half * 2 + 0] + bi.x;
                float v1 = acc[mf][nf][half * 2 + 1] + bi.y;
                if (QKV) {
                    float2 lo = *(const float2*)(lora + (size_t)r * D3 + c);
                    v0 += lo.x; v1 += lo.y;
                    int which = c >> 10, rr = c & 1023;
                    int h = rr >> 6, d = rr & 63;
                    int b_ = r >> 11, s = r & 2047;
                    float* dst = (which == 0) ? g_q : (which == 1) ? g_k : g_v;
                    // store tf32-RNA-rounded values (bit-exact with in-kernel cvt)
                    *(float2*)(dst + ((size_t)((b_ * NH + h) * SS + s)) * HD + d) =
                        make_float2(__uint_as_float(f2t(v0)), __uint_as_float(f2t(v1)));
                } else {
                    *(float2*)(C + (size_t)r * N + c) = make_float2(v0, v1);
                }
            }
        }
    }
}

// ---------------------------------------------------------------------------
// Flash attention, tf32 mma, causal. Block = (bh, 128-row q tile), 4 warps;
// warp w owns q rows w*32..w*32+31 (two 16-row m-fragments).
// K/V tiles double-buffered via cp.async — R12 structure (best known):
//   issue(j+1) -> wait_group 1 -> sync -> compute -> sync.
// Smem: Ks[2][64][68], Vs[2][64][72], Ps[128][68] (Ps doubles as Q staging).
// Epilogue stores g_attn pre-rounded to tf32 for the proj GEMM.
// ---------------------------------------------------------------------------
#define KSTR 68
#define VSTR 72
#define PSTR 68
#define FS_KB (64*KSTR)                 // words per K buffer
#define FS_VB (64*VSTR)                 // words per V buffer
#define OFF_V (2*FS_KB)
#define OFF_P (OFF_V + 2*FS_VB)
#define FSMEM ((OFF_P + 128*PSTR) * 4)  // 106496 bytes

__global__ __launch_bounds__(128, 2)
void flash_tf32()
{
    extern __shared__ unsigned smf[];
    unsigned* Ps = smf + OFF_P;

    const int qi = (int)gridDim.x - 1 - (int)blockIdx.x;   // heavy blocks first
    const int bh = blockIdx.y;
    const float* Qg = g_q + (size_t)bh * SS * HD;
    const float* Kg = g_k + (size_t)bh * SS * HD;
    const float* Vg = g_v + (size_t)bh * SS * HD;

    const int tid = threadIdx.x;
    const int warp = tid >> 5, lane = tid & 31;
    const int g = lane >> 2, t = lane & 3;
    const int rb = warp * 32;

    const unsigned sb = (unsigned)__cvta_generic_to_shared(smf);
    const int rr0 = tid >> 4, cw = (tid & 15) * 4;   // copy decomposition

    auto issue_tile = [&](int j, int buf) {
        const float* Kt = Kg + (size_t)j * 64 * HD;
        const float* Vt = Vg + (size_t)j * 64 * HD;
#pragma unroll
        for (int i = 0; i < 8; i++) {
            int r = rr0 + 8 * i;
            cpa16(sb + (buf * FS_KB + r * KSTR + cw) * 4u, Kt + r * HD + cw);
            cpa16(sb + (OFF_V + buf * FS_VB + r * VSTR + cw) * 4u, Vt + r * HD + cw);
        }
        asm volatile("cp.async.commit_group;\n" ::: "memory");
    };

    issue_tile(0, 0);

    // stage Q (raw pre-rounded bits) into Ps area: 128 rows x 64 d
#pragma unroll
    for (int i = 0; i < 16; i++) {
        int idx = tid + i * 128;
        int r = idx >> 4, d4 = (idx & 15) * 4;
        float4 q4 = *(const float4*)(Qg + (size_t)(qi * 128 + r) * HD + d4);
        *(uint4*)(Ps + r * PSTR + d4) =
            make_uint4(__float_as_uint(q4.x), __float_as_uint(q4.y),
                       __float_as_uint(q4.z), __float_as_uint(q4.w));
    }
    __syncthreads();

    // build Q fragments (scaled by 1/8; input already tf32 so scale is exact)
    unsigned qa[2][8][4];
#pragma unroll
    for (int mf = 0; mf < 2; mf++) {
        int r0 = rb + mf * 16 + g;
#pragma unroll
        for (int j8 = 0; j8 < 8; j8++) {
            qa[mf][j8][0] = f2t(__uint_as_float(Ps[r0 * PSTR + j8 * 8 + t]) * 0.125f);
            qa[mf][j8][1] = f2t(__uint_as_float(Ps[(r0 + 8) * PSTR + j8 * 8 + t]) * 0.125f);
            qa[mf][j8][2] = f2t(__uint_as_float(Ps[r0 * PSTR + j8 * 8 + t + 4]) * 0.125f);
            qa[mf][j8][3] = f2t(__uint_as_float(Ps[(r0 + 8) * PSTR + j8 * 8 + t + 4]) * 0.125f);
        }
    }

    float o[2][8][4];
#pragma unroll
    for (int mf = 0; mf < 2; mf++)
#pragma unroll
        for (int nf = 0; nf < 8; nf++)
#pragma unroll
            for (int e = 0; e < 4; e++) o[mf][nf][e] = 0.f;
    float ml[2] = {-1e30f, -1e30f}, mh[2] = {-1e30f, -1e30f};
    float ll[2] = {0.f, 0.f}, lh[2] = {0.f, 0.f};

    const int jmax = 2 * qi + 1;
    for (int j = 0; j <= jmax; j++) {
        if (j < jmax) {
            issue_tile(j + 1, (j + 1) & 1);
            asm volatile("cp.async.wait_group 1;\n" ::: "memory");
        } else {
            asm volatile("cp.async.wait_group 0;\n" ::: "memory");
        }
        __syncthreads();

        const unsigned* Ks = smf + (j & 1) * FS_KB;
        const unsigned* Vs = smf + OFF_V + (j & 1) * FS_VB;

        const bool act = !(j == jmax && warp < 2);
        if (act) {
            // S = Q K^T  (32 q rows x 64 keys)
            float s[2][8][4];
#pragma unroll
            for (int nf = 0; nf < 8; nf++) {
#pragma unroll
                for (int e = 0; e < 4; e++) { s[0][nf][e] = 0.f; s[1][nf][e] = 0.f; }
#pragma unroll
                for (int j8 = 0; j8 < 8; j8++) {
                    unsigned kb[2];
                    kb[0] = Ks[(nf * 8 + g) * KSTR + j8 * 8 + t];
                    kb[1] = Ks[(nf * 8 + g) * KSTR + j8 * 8 + t + 4];
                    mma8(s[0][nf], qa[0][j8], kb);
                    mma8(s[1][nf], qa[1][j8], kb);
                }
            }

            // causal mask (diagonal band only)
            if (j >= 2 * qi) {
#pragma unroll
                for (int mf = 0; mf < 2; mf++) {
                    int r0 = qi * 128 + rb + mf * 16 + g;
#pragma unroll
                    for (int nf = 0; nf < 8; nf++) {
                        int c0 = j * 64 + nf * 8 + 2 * t;
                        if (c0     > r0)     s[mf][nf][0] = -1e30f;
                        if (c0 + 1 > r0)     s[mf][nf][1] = -1e30f;
                        if (c0     > r0 + 8) s[mf][nf][2] = -1e30f;
                        if (c0 + 1 > r0 + 8) s[mf][nf][3] = -1e30f;
                    }
                }
            }

            // online softmax per m-frag (rows r0, r0+8)
#pragma unroll
            for (int mf = 0; mf < 2; mf++) {
                float mxl = -1e30f, mxh = -1e30f;
#pragma unroll
                for (int nf = 0; nf < 8; nf++) {
                    mxl = fmaxf(mxl, fmaxf(s[mf][nf][0], s[mf][nf][1]));
                    mxh = fmaxf(mxh, fmaxf(s[mf][nf][2], s[mf][nf][3]));
                }
                mxl = fmaxf(mxl, __shfl_xor_sync(0xffffffffu, mxl, 1));
                mxl = fmaxf(mxl, __shfl_xor_sync(0xffffffffu, mxl, 2));
                mxh = fmaxf(mxh, __shfl_xor_sync(0xffffffffu, mxh, 1));
                mxh = fmaxf(mxh, __shfl_xor_sync(0xffffffffu, mxh, 2));
                float nml = fmaxf(ml[mf], mxl), nmh = fmaxf(mh[mf], mxh);
                float cl = __expf(ml[mf] - nml), ch = __expf(mh[mf] - nmh);
                float suml = 0.f, sumh = 0.f;
#pragma unroll
                for (int nf = 0; nf < 8; nf++) {
                    s[mf][nf][0] = __expf(s[mf][nf][0] - nml);
                    s[mf][nf][1] = __expf(s[mf][nf][1] - nml);
                    s[mf][nf][2] = __expf(s[mf][nf][2] - nmh);
                    s[mf][nf][3] = __expf(s[mf][nf][3] - nmh);
                    suml += s[mf][nf][0] + s[mf][nf][1];
                    sumh += s[mf][nf][2] + s[mf][nf][3];
                }
                suml += __shfl_xor_sync(0xffffffffu, suml, 1);
                suml += __shfl_xor_sync(0xffffffffu, suml, 2);
                sumh += __shfl_xor_sync(0xffffffffu, sumh, 1);
                sumh += __shfl_xor_sync(0xffffffffu, sumh, 2);
                ll[mf] = ll[mf] * cl + suml; lh[mf] = lh[mf] * ch + sumh;
                ml[mf] = nml; mh[mf] = nmh;
#pragma unroll
                for (int nf = 0; nf < 8; nf++) {
                    o[mf][nf][0] *= cl; o[mf][nf][1] *= cl;
                    o[mf][nf][2] *= ch; o[mf][nf][3] *= ch;
                }

                int r0 = rb + mf * 16 + g;
#pragma unroll
                for (int nf = 0; nf < 8; nf++) {
                    *(uint2*)(Ps + r0 * PSTR + nf * 8 + 2 * t) =
                        make_uint2(f2t(s[mf][nf][0]), f2t(s[mf][nf][1]));
                    *(uint2*)(Ps + (r0 + 8) * PSTR + nf * 8 + 2 * t) =
                        make_uint2(f2t(s[mf][nf][2]), f2t(s[mf][nf][3]));
                }
            }
            __syncwarp();

            // O += P V  (P frags via smem, V frags shared across m-frags)
#pragma unroll
            for (int j8 = 0; j8 < 8; j8++) {
                unsigned pa[2][4];
#pragma unroll
                for (int mf = 0; mf < 2; mf++) {
                    int r0 = rb + mf * 16 + g;
                    pa[mf][0] = Ps[r0 * PSTR + j8 * 8 + t];
                    pa[mf][1] = Ps[(r0 + 8) * PSTR + j8 * 8 + t];
                    pa[mf][2] = Ps[r0 * PSTR + j8 * 8 + t + 4];
                    pa[mf][3] = Ps[(r0 + 8) * PSTR + j8 * 8 + t + 4];
                }
#pragma unroll
                for (int nf = 0; nf < 8; nf++) {
                    unsigned vb[2];
                    vb[0] = Vs[(j8 * 8 + t) * VSTR + nf * 8 + g];
                    vb[1] = Vs[(j8 * 8 + t + 4) * VSTR + nf * 8 + g];
                    mma8(o[0][nf], pa[0], vb);
                    mma8(o[1][nf], pa[1], vb);
                }
            }
        }

        if (j < jmax) __syncthreads();
    }

    // normalize + store merged heads, pre-rounded to tf32 for the proj GEMM
    const int b_ = bh >> 4, h = bh & 15;
#pragma unroll
    for (int mf = 0; mf < 2; mf++) {
        float rl = 1.f / ll[mf], rh = 1.f / lh[mf];
        int rlo = qi * 128 + rb + mf * 16 + g, rhi = rlo + 8;
#pragma unroll
        for (int nf = 0; nf < 8; nf++) {
            int d = nf * 8 + 2 * t;
            *(float2*)(g_attn + (size_t)(b_ * SS + rlo) * DD + h * HD + d) =
                make_float2(__uint_as_float(f2t(o[mf][nf][0] * rl)),
                            __uint_as_float(f2t(o[mf][nf][1] * rl)));
            *(float2*)(g_attn + (size_t)(b_ * SS + rhi) * DD + h * HD + d) =
                make_float2(__uint_as_float(f2t(o[mf][nf][2] * rh)),
                            __uint_as_float(f2t(o[mf][nf][3] * rh)));
        }
    }
}

// ---------------------------------------------------------------------------
extern "C" void kernel_launch(void* const* d_in, const int* in_sizes, int n_in,
                              void* d_out, int out_size)
{
    const float* hs     = (const float*)d_in[0];
    const float* lora   = (const float*)d_in[1];
    const float* w_attn = (const float*)d_in[2];
    const float* b_attn = (const float*)d_in[3];
    const float* w_proj = (const float*)d_in[4];
    const float* b_proj = (const float*)d_in[5];
    float* out = (float*)d_out;

    cudaFuncSetAttribute(gemm_tf32<D3, true>,
                         cudaFuncAttributeMaxDynamicSharedMemorySize, GSMEM);
    cudaFuncSetAttribute(gemm_tf32<DD, false>,
                         cudaFuncAttributeMaxDynamicSharedMemorySize, GSMEM);
    cudaFuncSetAttribute(flash_tf32,
                         cudaFuncAttributeMaxDynamicSharedMemorySize, FSMEM);

    // device-global symbol addresses (host side) — REQUIRED for passing
    // __device__ arrays as kernel arguments from host code.
    float *p_a, *p_w, *p_wp, *p_attn;
    cudaGetSymbolAddress((void**)&p_a,    g_a);
    cudaGetSymbolAddress((void**)&p_w,    g_w);
    cudaGetSymbolAddress((void**)&p_wp,   g_wp);
    cudaGetSymbolAddress((void**)&p_attn, g_attn);

    // pre-round operands to tf32 (bit-exact with previous in-kernel cvt)
    round_tf32<<<(MTOT*DD/4 + 255)/256, 256>>>((const float4*)hs,     (float4*)p_a,  MTOT*DD/4);
    round_tf32<<<(DD*D3/4   + 255)/256, 256>>>((const float4*)w_attn, (float4*)p_w,  DD*D3/4);
    round_tf32<<<(DD*DD/4   + 255)/256, 256>>>((const float4*)w_proj, (float4*)p_wp, DD*DD/4);

    gemm_tf32<D3, true><<<dim3(D3 / 128, MTOT / 128), 128, GSMEM>>>(
        p_a, p_w, b_attn, lora, nullptr);
    flash_tf32<<<dim3(SS / 128, NB * NH), 128, FSMEM>>>();
    gemm_tf32<DD, false><<<dim3(DD / 128, MTOT / 128), 128, GSMEM>>>(
        p_attn, p_wp, b_proj, nullptr, out);
}

// round 16
// speedup vs baseline: 1.1237x; 1.1237x over previous
#include <cuda_runtime.h>
#include <math.h>

#define NB 2
#define SS 2048
#define NH 16
#define HD 64
#define DD 1024
#define D3 3072
#define MTOT (NB*SS)

// Scratch (allocation-free rule: device globals)
__device__ float g_q[NB*NH*SS*HD];     // [B,H,S,hd] (pre-rounded tf32)
__device__ float g_k[NB*NH*SS*HD];
__device__ float g_v[NB*NH*SS*HD];
__device__ float g_attn[MTOT*DD];      // merged heads [B*S, D] (pre-rounded tf32)
__device__ float g_a[MTOT*DD];         // rounded hidden_states
__device__ float g_w[DD*D3];           // rounded w_attn
__device__ float g_wp[DD*DD];          // rounded w_proj

__device__ __forceinline__ unsigned f2t(float x) {
    unsigned u;
    asm("cvt.rna.tf32.f32 %0, %1;" : "=r"(u) : "f"(x));
    return u;
}

__device__ __forceinline__ void mma8(float* d, const unsigned* a, const unsigned* b) {
    asm volatile(
        "mma.sync.aligned.m16n8k8.row.col.f32.tf32.tf32.f32 "
        "{%0,%1,%2,%3}, {%4,%5,%6,%7}, {%8,%9}, {%0,%1,%2,%3};\n"
        : "+f"(d[0]), "+f"(d[1]), "+f"(d[2]), "+f"(d[3])
        : "r"(a[0]), "r"(a[1]), "r"(a[2]), "r"(a[3]), "r"(b[0]), "r"(b[1]));
}

__device__ __forceinline__ void cpa16(unsigned dst, const float* src) {
    asm volatile("cp.async.cg.shared.global [%0], [%1], 16;\n" :: "r"(dst), "l"(src));
}

// ---------------------------------------------------------------------------
// Merged pre-round: one launch rounds hs, w_attn, w_proj to RNA-tf32.
// Segments (in float4 units): [0, A4) -> g_a, [A4, A4+W4) -> g_w, rest -> g_wp.
// ---------------------------------------------------------------------------
#define A4 (MTOT*DD/4)
#define W4 (DD*D3/4)
#define P4 (DD*DD/4)
#define RND_TOT (A4 + W4 + P4)

__global__ __launch_bounds__(256)
void round_all(const float4* __restrict__ hs, const float4* __restrict__ wa,
               const float4* __restrict__ wp,
               float4* __restrict__ da, float4* __restrict__ dw,
               float4* __restrict__ dp)
{
    int i = blockIdx.x * blockDim.x + threadIdx.x;
    if (i >= RND_TOT) return;
    const float4* src; float4* dst; int off;
    if (i < A4)            { src = hs; dst = da; off = i; }
    else if (i < A4 + W4)  { src = wa; dst = dw; off = i - A4; }
    else                   { src = wp; dst = dp; off = i - A4 - W4; }
    float4 v = src[off];
    dst[off] = make_float4(__uint_as_float(f2t(v.x)), __uint_as_float(f2t(v.y)),
                           __uint_as_float(f2t(v.z)), __uint_as_float(f2t(v.w)));
}

// ---------------------------------------------------------------------------
// TF32 GEMM: C[M,N] = A[M,1024] @ W[1024,N] (+bias) (+lora, scatter q/k/v)
// 128x128 CTA tile, BK=32, 128 threads (4 warps 2x2), warp tile 64x64.
// cp.async double-buffered, R12 schedule (best known):
//   issue(it+1) -> wait_group 1 -> sync -> compute -> sync.
// __launch_bounds__(128,2): 2 CTAs/SM, regs 255 (R12-exact; 3-CTA cap spills).
// ---------------------------------------------------------------------------
#define ASTR 36
#define BSTR 136
#define ABUF (128*ASTR)          // 4608 u32
#define BBUF (32*BSTR)           // 4352 u32
#define GBUF (ABUF + BBUF)       // per stage
#define GSMEM (2*GBUF*4)         // bytes = 71680

template<int N, bool QKV>
__global__ __launch_bounds__(128, 2)
void gemm_tf32(const float* __restrict__ A, const float* __restrict__ W,
               const float* __restrict__ bias, const float* __restrict__ lora,
               float* __restrict__ C)
{
    extern __shared__ unsigned sg[];
    const int K = DD;

    const int tid  = threadIdx.x;
    const int warp = tid >> 5, lane = tid & 31;
    const int g = lane >> 2, t = lane & 3;
    const int wm = warp & 1, wn = warp >> 1;         // 2 x 2 warps
    const int bm = blockIdx.y * 128, bn = blockIdx.x * 128;

    const unsigned sbA = (unsigned)__cvta_generic_to_shared(sg);
    const unsigned sbB = sbA + ABUF * 4;

    // issue cp.async for k-tile `it` into stage `buf`
    auto issue = [&](int it, int buf) {
        const unsigned stg = (unsigned)buf * (GBUF * 4);
        const int k0 = it * 32;
#pragma unroll
        for (int i = 0; i < 8; i++) {
            int c = tid + 128 * i;
            int row = c >> 3, kq = c & 7;
            cpa16(sbA + stg + (row * ASTR + kq * 4) * 4,
                  A + (size_t)(bm + row) * K + k0 + kq * 4);
        }
#pragma unroll
        for (int i = 0; i < 8; i++) {
            int c = tid + 128 * i;
            int k = c >> 5, nq = c & 31;
            cpa16(sbB + stg + (k * BSTR + nq * 4) * 4,
                  W + (size_t)(k0 + k) * N + bn + nq * 4);
        }
        asm volatile("cp.async.commit_group;\n" ::: "memory");
    };

    float acc[4][8][4];
#pragma unroll
    for (int mf = 0; mf < 4; mf++)
#pragma unroll
        for (int nf = 0; nf < 8; nf++)
#pragma unroll
            for (int e = 0; e < 4; e++) acc[mf][nf][e] = 0.f;

    issue(0, 0);

    const int NT = K / 32;
    for (int it = 0; it < NT; ++it) {
        if (it < NT - 1) {
            issue(it + 1, (it + 1) & 1);
            asm volatile("cp.async.wait_group 1;\n" ::: "memory");
        } else {
            asm volatile("cp.async.wait_group 0;\n" ::: "memory");
        }
        __syncthreads();

        const unsigned* Ac = sg + (it & 1) * GBUF;
        const unsigned* Bc = Ac + ABUF;
#pragma unroll
        for (int ks = 0; ks < 4; ks++) {
            const int kb = ks * 8;
            unsigned ua[4][4];
#pragma unroll
            for (int mf = 0; mf < 4; mf++) {
                int rbm = wm * 64 + mf * 16;
                ua[mf][0] = Ac[(rbm + g) * ASTR + kb + t];
                ua[mf][1] = Ac[(rbm + g + 8) * ASTR + kb + t];
                ua[mf][2] = Ac[(rbm + g) * ASTR + kb + t + 4];
                ua[mf][3] = Ac[(rbm + g + 8) * ASTR + kb + t + 4];
            }
#pragma unroll
            for (int nf = 0; nf < 8; nf++) {
                unsigned ub[2];
                int col = wn * 64 + nf * 8 + g;
                ub[0] = Bc[(kb + t) * BSTR + col];
                ub[1] = Bc[(kb + t + 4) * BSTR + col];
                mma8(acc[0][nf], ua[0], ub);
                mma8(acc[1][nf], ua[1], ub);
                mma8(acc[2][nf], ua[2], ub);
                mma8(acc[3][nf], ua[3], ub);
            }
        }

        if (it < NT - 1) __syncthreads();   // all done reading this buf
    }

    // epilogue
#pragma unroll
    for (int mf = 0; mf < 4; mf++) {
#pragma unroll
        for (int nf = 0; nf < 8; nf++) {
            int c = bn + wn * 64 + nf * 8 + 2 * t;
            float2 bi = *(const float2*)(bias + c);
#pragma unroll
            for (int half = 0; half < 2; half++) {
                int r = bm + wm * 64 + mf * 16 + g + half * 8;
                float v0 = acc[mf][nf][half * 2 + 0] + bi.x;
                float v1 = acc[mf][nf][half * 2 + 1] + bi.y;
                if (QKV) {
                    float2 lo = *(const float2*)(lora + (size_t)r * D3 + c);
                    v0 += lo.x; v1 += lo.y;
                    int which = c >> 10, rr = c & 1023;
                    int h = rr >> 6, d = rr & 63;
                    int b_ = r >> 11, s = r & 2047;
                    float* dst = (which == 0) ? g_q : (which == 1) ? g_k : g_v;
                    // store tf32-RNA-rounded values (bit-exact with in-kernel cvt)
                    *(float2*)(dst + ((size_t)((b_ * NH + h) * SS + s)) * HD + d) =
                        make_float2(__uint_as_float(f2t(v0)), __uint_as_float(f2t(v1)));
                } else {
                    *(float2*)(C + (size_t)r * N + c) = make_float2(v0, v1);
                }
            }
        }
    }
}

// ---------------------------------------------------------------------------
// Flash attention, tf32 mma, causal. Block = (bh, 128-row q tile), 4 warps;
// warp w owns q rows w*32..w*32+31 (two 16-row m-fragments).
// K/V tiles double-buffered via cp.async — R12 structure (best known):
//   issue(j+1) -> wait_group 1 -> sync -> compute -> sync.
// Smem: Ks[2][64][68], Vs[2][64][72], Ps[128][68] (Ps doubles as Q staging).
// Epilogue stores g_attn pre-rounded to tf32 for the proj GEMM.
// ---------------------------------------------------------------------------
#define KSTR 68
#define VSTR 72
#define PSTR 68
#define FS_KB (64*KSTR)                 // words per K buffer
#define FS_VB (64*VSTR)                 // words per V buffer
#define OFF_V (2*FS_KB)
#define OFF_P (OFF_V + 2*FS_VB)
#define FSMEM ((OFF_P + 128*PSTR) * 4)  // 106496 bytes

__global__ __launch_bounds__(128, 2)
void flash_tf32()
{
    extern __shared__ unsigned smf[];
    unsigned* Ps = smf + OFF_P;

    const int qi = (int)gridDim.x - 1 - (int)blockIdx.x;   // heavy blocks first
    const int bh = blockIdx.y;
    const float* Qg = g_q + (size_t)bh * SS * HD;
    const float* Kg = g_k + (size_t)bh * SS * HD;
    const float* Vg = g_v + (size_t)bh * SS * HD;

    const int tid = threadIdx.x;
    const int warp = tid >> 5, lane = tid & 31;
    const int g = lane >> 2, t = lane & 3;
    const int rb = warp * 32;

    const unsigned sb = (unsigned)__cvta_generic_to_shared(smf);
    const int rr0 = tid >> 4, cw = (tid & 15) * 4;   // copy decomposition

    auto issue_tile = [&](int j, int buf) {
        const float* Kt = Kg + (size_t)j * 64 * HD;
        const float* Vt = Vg + (size_t)j * 64 * HD;
#pragma unroll
        for (int i = 0; i < 8; i++) {
            int r = rr0 + 8 * i;
            cpa16(sb + (buf * FS_KB + r * KSTR + cw) * 4u, Kt + r * HD + cw);
            cpa16(sb + (OFF_V + buf * FS_VB + r * VSTR + cw) * 4u, Vt + r * HD + cw);
        }
        asm volatile("cp.async.commit_group;\n" ::: "memory");
    };

    issue_tile(0, 0);

    // stage Q (raw pre-rounded bits) into Ps area: 128 rows x 64 d
#pragma unroll
    for (int i = 0; i < 16; i++) {
        int idx = tid + i * 128;
        int r = idx >> 4, d4 = (idx & 15) * 4;
        float4 q4 = *(const float4*)(Qg + (size_t)(qi * 128 + r) * HD + d4);
        *(uint4*)(Ps + r * PSTR + d4) =
            make_uint4(__float_as_uint(q4.x), __float_as_uint(q4.y),
                       __float_as_uint(q4.z), __float_as_uint(q4.w));
    }
    __syncthreads();

    // build Q fragments (scaled by 1/8; input already tf32 so scale is exact)
    unsigned qa[2][8][4];
#pragma unroll
    for (int mf = 0; mf < 2; mf++) {
        int r0 = rb + mf * 16 + g;
#pragma unroll
        for (int j8 = 0; j8 < 8; j8++) {
            qa[mf][j8][0] = f2t(__uint_as_float(Ps[r0 * PSTR + j8 * 8 + t]) * 0.125f);
            qa[mf][j8][1] = f2t(__uint_as_float(Ps[(r0 + 8) * PSTR + j8 * 8 + t]) * 0.125f);
            qa[mf][j8][2] = f2t(__uint_as_float(Ps[r0 * PSTR + j8 * 8 + t + 4]) * 0.125f);
            qa[mf][j8][3] = f2t(__uint_as_float(Ps[(r0 + 8) * PSTR + j8 * 8 + t + 4]) * 0.125f);
        }
    }

    float o[2][8][4];
#pragma unroll
    for (int mf = 0; mf < 2; mf++)
#pragma unroll
        for (int nf = 0; nf < 8; nf++)
#pragma unroll
            for (int e = 0; e < 4; e++) o[mf][nf][e] = 0.f;
    float ml[2] = {-1e30f, -1e30f}, mh[2] = {-1e30f, -1e30f};
    float ll[2] = {0.f, 0.f}, lh[2] = {0.f, 0.f};

    const int jmax = 2 * qi + 1;
    for (int j = 0; j <= jmax; j++) {
        if (j < jmax) {
            issue_tile(j + 1, (j + 1) & 1);
            asm volatile("cp.async.wait_group 1;\n" ::: "memory");
        } else {
            asm volatile("cp.async.wait_group 0;\n" ::: "memory");
        }
        __syncthreads();

        const unsigned* Ks = smf + (j & 1) * FS_KB;
        const unsigned* Vs = smf + OFF_V + (j & 1) * FS_VB;

        const bool act = !(j == jmax && warp < 2);
        if (act) {
            // S = Q K^T  (32 q rows x 64 keys)
            float s[2][8][4];
#pragma unroll
            for (int nf = 0; nf < 8; nf++) {
#pragma unroll
                for (int e = 0; e < 4; e++) { s[0][nf][e] = 0.f; s[1][nf][e] = 0.f; }
#pragma unroll
                for (int j8 = 0; j8 < 8; j8++) {
                    unsigned kb[2];
                    kb[0] = Ks[(nf * 8 + g) * KSTR + j8 * 8 + t];
                    kb[1] = Ks[(nf * 8 + g) * KSTR + j8 * 8 + t + 4];
                    mma8(s[0][nf], qa[0][j8], kb);
                    mma8(s[1][nf], qa[1][j8], kb);
                }
            }

            // causal mask (diagonal band only)
            if (j >= 2 * qi) {
#pragma unroll
                for (int mf = 0; mf < 2; mf++) {
                    int r0 = qi * 128 + rb + mf * 16 + g;
#pragma unroll
                    for (int nf = 0; nf < 8; nf++) {
                        int c0 = j * 64 + nf * 8 + 2 * t;
                        if (c0     > r0)     s[mf][nf][0] = -1e30f;
                        if (c0 + 1 > r0)     s[mf][nf][1] = -1e30f;
                        if (c0     > r0 + 8) s[mf][nf][2] = -1e30f;
                        if (c0 + 1 > r0 + 8) s[mf][nf][3] = -1e30f;
                    }
                }
            }

            // online softmax per m-frag (rows r0, r0+8)
#pragma unroll
            for (int mf = 0; mf < 2; mf++) {
                float mxl = -1e30f, mxh = -1e30f;
#pragma unroll
                for (int nf = 0; nf < 8; nf++) {
                    mxl = fmaxf(mxl, fmaxf(s[mf][nf][0], s[mf][nf][1]));
                    mxh = fmaxf(mxh, fmaxf(s[mf][nf][2], s[mf][nf][3]));
                }
                mxl = fmaxf(mxl, __shfl_xor_sync(0xffffffffu, mxl, 1));
                mxl = fmaxf(mxl, __shfl_xor_sync(0xffffffffu, mxl, 2));
                mxh = fmaxf(mxh, __shfl_xor_sync(0xffffffffu, mxh, 1));
                mxh = fmaxf(mxh, __shfl_xor_sync(0xffffffffu, mxh, 2));
                float nml = fmaxf(ml[mf], mxl), nmh = fmaxf(mh[mf], mxh);
                float cl = __expf(ml[mf] - nml), ch = __expf(mh[mf] - nmh);
                float suml = 0.f, sumh = 0.f;
#pragma unroll
                for (int nf = 0; nf < 8; nf++) {
                    s[mf][nf][0] = __expf(s[mf][nf][0] - nml);
                    s[mf][nf][1] = __expf(s[mf][nf][1] - nml);
                    s[mf][nf][2] = __expf(s[mf][nf][2] - nmh);
                    s[mf][nf][3] = __expf(s[mf][nf][3] - nmh);
                    suml += s[mf][nf][0] + s[mf][nf][1];
                    sumh += s[mf][nf][2] + s[mf][nf][3];
                }
                suml += __shfl_xor_sync(0xffffffffu, suml, 1);
                suml += __shfl_xor_sync(0xffffffffu, suml, 2);
                sumh += __shfl_xor_sync(0xffffffffu, sumh, 1);
                sumh += __shfl_xor_sync(0xffffffffu, sumh, 2);
                ll[mf] = ll[mf] * cl + suml; lh[mf] = lh[mf] * ch + sumh;
                ml[mf] = nml; mh[mf] = nmh;
#pragma unroll
                for (int nf = 0; nf < 8; nf++) {
                    o[mf][nf][0] *= cl; o[mf][nf][1] *= cl;
                    o[mf][nf][2] *= ch; o[mf][nf][3] *= ch;
                }

                int r0 = rb + mf * 16 + g;
#pragma unroll
                for (int nf = 0; nf < 8; nf++) {
                    *(uint2*)(Ps + r0 * PSTR + nf * 8 + 2 * t) =
                        make_uint2(f2t(s[mf][nf][0]), f2t(s[mf][nf][1]));
                    *(uint2*)(Ps + (r0 + 8) * PSTR + nf * 8 + 2 * t) =
                        make_uint2(f2t(s[mf][nf][2]), f2t(s[mf][nf][3]));
                }
            }
            __syncwarp();

            // O += P V  (P frags via smem, V frags shared across m-frags)
#pragma unroll
            for (int j8 = 0; j8 < 8; j8++) {
                unsigned pa[2][4];
#pragma unroll
                for (int mf = 0; mf < 2; mf++) {
                    int r0 = rb + mf * 16 + g;
                    pa[mf][0] = Ps[r0 * PSTR + j8 * 8 + t];
                    pa[mf][1] = Ps[(r0 + 8) * PSTR + j8 * 8 + t];
                    pa[mf][2] = Ps[r0 * PSTR + j8 * 8 + t + 4];
                    pa[mf][3] = Ps[(r0 + 8) * PSTR + j8 * 8 + t + 4];
                }
#pragma unroll
                for (int nf = 0; nf < 8; nf++) {
                    unsigned vb[2];
                    vb[0] = Vs[(j8 * 8 + t) * VSTR + nf * 8 + g];
                    vb[1] = Vs[(j8 * 8 + t + 4) * VSTR + nf * 8 + g];
                    mma8(o[0][nf], pa[0], vb);
                    mma8(o[1][nf], pa[1], vb);
                }
            }
        }

        if (j < jmax) __syncthreads();
    }

    // normalize + store merged heads, pre-rounded to tf32 for the proj GEMM
    const int b_ = bh >> 4, h = bh & 15;
#pragma unroll
    for (int mf = 0; mf < 2; mf++) {
        float rl = 1.f / ll[mf], rh = 1.f / lh[mf];
        int rlo = qi * 128 + rb + mf * 16 + g, rhi = rlo + 8;
#pragma unroll
        for (int nf = 0; nf < 8; nf++) {
            int d = nf * 8 + 2 * t;
            *(float2*)(g_attn + (size_t)(b_ * SS + rlo) * DD + h * HD + d) =
                make_float2(__uint_as_float(f2t(o[mf][nf][0] * rl)),
                            __uint_as_float(f2t(o[mf][nf][1] * rl)));
            *(float2*)(g_attn + (size_t)(b_ * SS + rhi) * DD + h * HD + d) =
                make_float2(__uint_as_float(f2t(o[mf][nf][2] * rh)),
                            __uint_as_float(f2t(o[mf][nf][3] * rh)));
        }
    }
}

// ---------------------------------------------------------------------------
extern "C" void kernel_launch(void* const* d_in, const int* in_sizes, int n_in,
                              void* d_out, int out_size)
{
    const float* hs     = (const float*)d_in[0];
    const float* lora   = (const float*)d_in[1];
    const float* w_attn = (const float*)d_in[2];
    const float* b_attn = (const float*)d_in[3];
    const float* w_proj = (const float*)d_in[4];
    const float* b_proj = (const float*)d_in[5];
    float* out = (float*)d_out;

    cudaFuncSetAttribute(gemm_tf32<D3, true>,
                         cudaFuncAttributeMaxDynamicSharedMemorySize, GSMEM);
    cudaFuncSetAttribute(gemm_tf32<DD, false>,
                         cudaFuncAttributeMaxDynamicSharedMemorySize, GSMEM);
    cudaFuncSetAttribute(flash_tf32,
                         cudaFuncAttributeMaxDynamicSharedMemorySize, FSMEM);

    // device-global symbol addresses (host side) — REQUIRED for passing
    // __device__ arrays as kernel arguments from host code.
    float *p_a, *p_w, *p_wp, *p_attn;
    cudaGetSymbolAddress((void**)&p_a,    g_a);
    cudaGetSymbolAddress((void**)&p_w,    g_w);
    cudaGetSymbolAddress((void**)&p_wp,   g_wp);
    cudaGetSymbolAddress((void**)&p_attn, g_attn);

    // single merged pre-round launch (bit-exact with previous 3 launches)
    round_all<<<(RND_TOT + 255) / 256, 256>>>(
        (const float4*)hs, (const float4*)w_attn, (const float4*)w_proj,
        (float4*)p_a, (float4*)p_w, (float4*)p_wp);

    gemm_tf32<D3, true><<<dim3(D3 / 128, MTOT / 128), 128, GSMEM>>>(
        p_a, p_w, b_attn, lora, nullptr);
    flash_tf32<<<dim3(SS / 128, NB * NH), 128, FSMEM>>>();
    gemm_tf32<DD, false><<<dim3(DD / 128, MTOT / 128), 128, GSMEM>>>(
        p_attn, p_wp, b_proj, nullptr, out);
}